// round 2
// baseline (speedup 1.0000x reference)
#include <cuda_runtime.h>
#include <cuda_bf16.h>

#define NMAX 100000
#define D 64

// Scratch (no allocations allowed) — __device__ globals.
__device__ float g_deg[NMAX];
__device__ float g_dinv[NMAX];
__device__ float g_xh[(size_t)NMAX * D];

// ---------------------------------------------------------------------------
// k0: zero output + degree scratch
// ---------------------------------------------------------------------------
__global__ void k_zero(float* __restrict__ out, int n_out, int n_nodes) {
    int i = blockIdx.x * blockDim.x + threadIdx.x;
    int stride = gridDim.x * blockDim.x;
    for (int j = i; j < n_out; j += stride) out[j] = 0.0f;
    for (int j = i; j < n_nodes; j += stride) g_deg[j] = 0.0f;
}

// ---------------------------------------------------------------------------
// k1: degree count from row indices (edge_index[0, :])  — int32 indices
// ---------------------------------------------------------------------------
__global__ void k_degree(const int* __restrict__ rowp, int E) {
    int i = blockIdx.x * blockDim.x + threadIdx.x;
    int stride = gridDim.x * blockDim.x;
    for (int e = i; e < E; e += stride) {
        atomicAdd(&g_deg[rowp[e]], 1.0f);
    }
}

// ---------------------------------------------------------------------------
// k2: dinv_sqrt = deg > 0 ? rsqrt(deg) : 0
// ---------------------------------------------------------------------------
__global__ void k_dinv(int N) {
    int i = blockIdx.x * blockDim.x + threadIdx.x;
    if (i < N) {
        float d = g_deg[i];
        g_dinv[i] = (d > 0.0f) ? rsqrtf(d) : 0.0f;
    }
}

// ---------------------------------------------------------------------------
// k3: xh = x @ W^T   (x: [N,64], W: [64,64] row-major; xh[n][o] = sum_k x[n][k]*W[o][k])
// block = (64, 4): tx = output feature, ty = row within 4-row group
// ---------------------------------------------------------------------------
__global__ void k_gemm(const float* __restrict__ x, const float* __restrict__ W, int N) {
    __shared__ float Ws[D][D + 1];   // +1 pad: Ws[o][k] bank = (o+k)%32 -> conflict-free col reads
    __shared__ float xs[4][D];

    int tx = threadIdx.x;            // 0..63
    int ty = threadIdx.y;            // 0..3
    int tid = ty * D + tx;

    for (int i = tid; i < D * D; i += 256) {
        Ws[i / D][i % D] = W[i];
    }
    __syncthreads();

    for (int rb = blockIdx.x * 4; rb < N; rb += gridDim.x * 4) {
        int r = rb + ty;
        if (r < N) xs[ty][tx] = x[(size_t)r * D + tx];
        __syncthreads();
        if (r < N) {
            float acc = 0.0f;
#pragma unroll
            for (int k = 0; k < D; k++) {
                acc = fmaf(xs[ty][k], Ws[tx][k], acc);
            }
            g_xh[(size_t)r * D + tx] = acc;
        }
        __syncthreads();
    }
}

// ---------------------------------------------------------------------------
// k4: edge scatter — one warp per edge.
// out[row] += dinv[row]*dinv[col] * xh[col]   (64 floats, 2 per lane)
// ---------------------------------------------------------------------------
__global__ void k_scatter(const int* __restrict__ ei, float* __restrict__ out, int E) {
    int gtid = blockIdx.x * blockDim.x + threadIdx.x;
    int warp = gtid >> 5;
    int lane = threadIdx.x & 31;
    int nwarps = (gridDim.x * blockDim.x) >> 5;

    const int* rowp = ei;
    const int* colp = ei + E;

    for (int e = warp; e < E; e += nwarps) {
        int r = rowp[e];
        int c = colp[e];
        float w = g_dinv[r] * g_dinv[c];
        const float* src = &g_xh[(size_t)c * D];
        float* dst = &out[(size_t)r * D];
        float v0 = w * src[lane];
        float v1 = w * src[lane + 32];
        atomicAdd(&dst[lane], v0);
        atomicAdd(&dst[lane + 32], v1);
    }
}

// ---------------------------------------------------------------------------
// launch
// ---------------------------------------------------------------------------
extern "C" void kernel_launch(void* const* d_in, const int* in_sizes, int n_in,
                              void* d_out, int out_size) {
    const int*   edge_index = (const int*)d_in[0];
    const float* x          = (const float*)d_in[1];
    const float* W          = (const float*)d_in[2];
    float*       out        = (float*)d_out;

    int E = in_sizes[0] / 2;
    int N = in_sizes[1] / D;

    k_zero<<<2048, 256>>>(out, out_size, N);
    k_degree<<<2048, 256>>>(edge_index, E);
    k_dinv<<<(N + 255) / 256, 256>>>(N);

    dim3 gemm_block(64, 4);
    int gemm_blocks = (N + 3) / 4;
    if (gemm_blocks > 25000) gemm_blocks = 25000;
    k_gemm<<<gemm_blocks, gemm_block>>>(x, W, N);

    k_scatter<<<4096, 256>>>(edge_index, out, E);
}

// round 4
// speedup vs baseline: 1.4107x; 1.4107x over previous
#include <cuda_runtime.h>
#include <cuda_bf16.h>

#define NMAX 100000
#define D 64

__device__ float g_deg[NMAX];
__device__ float g_dinv[NMAX];
__device__ float g_xh[(size_t)NMAX * D];

// packed fp32x2 FMA (Blackwell): d = a*b + c elementwise on 2 packed floats
__device__ __forceinline__ void fma_f32x2(unsigned long long& d,
                                          unsigned long long a,
                                          unsigned long long b,
                                          unsigned long long c) {
    asm("fma.rn.f32x2 %0, %1, %2, %3;" : "=l"(d) : "l"(a), "l"(b), "l"(c));
}

// ---------------------------------------------------------------------------
// k0: zero output + degree scratch
// ---------------------------------------------------------------------------
__global__ void k_zero(float* __restrict__ out, int n_out, int n_nodes) {
    int i = blockIdx.x * blockDim.x + threadIdx.x;
    int stride = gridDim.x * blockDim.x;
    for (int j = i; j < n_out; j += stride) out[j] = 0.0f;
    for (int j = i; j < n_nodes; j += stride) g_deg[j] = 0.0f;
}

// ---------------------------------------------------------------------------
// k1: degree count
// ---------------------------------------------------------------------------
__global__ void k_degree(const int* __restrict__ rowp, int E) {
    int i = blockIdx.x * blockDim.x + threadIdx.x;
    int stride = gridDim.x * blockDim.x;
    for (int e = i; e < E; e += stride) {
        atomicAdd(&g_deg[rowp[e]], 1.0f);
    }
}

// ---------------------------------------------------------------------------
// k2: dinv_sqrt
// ---------------------------------------------------------------------------
__global__ void k_dinv(int N) {
    int i = blockIdx.x * blockDim.x + threadIdx.x;
    if (i < N) {
        float d = g_deg[i];
        g_dinv[i] = (d > 0.0f) ? rsqrtf(d) : 0.0f;
    }
}

// ---------------------------------------------------------------------------
// k3: xh = x @ W^T  — W-stationary in registers (packed f32x2), 32 rows/block-iter
// block = 256 threads: tx = tid%64 -> output feature o, ty = tid/64 -> row group
// Each thread: 8 rows x 1 feature, inner loop = 32 x (LDS.64 broadcast + FMA2)
// ---------------------------------------------------------------------------
#define GEMM_ROWS 32   // rows per block iteration
#define RPT 8          // rows per thread (GEMM_ROWS / 4 ty-groups)

__global__ void __launch_bounds__(256) k_gemm(const float* __restrict__ x,
                                              const float* __restrict__ W, int N) {
    __shared__ float Ws[D * (D + 1)];          // staged W, padded rows
    __shared__ float2 xs[GEMM_ROWS][D / 2];    // x tile, float2 over k

    int tid = threadIdx.x;
    int tx = tid & 63;        // output feature o
    int ty = tid >> 6;        // 0..3

    // stage W coalesced, then pack thread's row into 32 f32x2 registers
    for (int i = tid; i < D * D; i += 256) {
        Ws[(i >> 6) * (D + 1) + (i & 63)] = W[i];
    }
    __syncthreads();

    unsigned long long w2[D / 2];
#pragma unroll
    for (int k2 = 0; k2 < D / 2; k2++) {
        float lo = Ws[tx * (D + 1) + 2 * k2];
        float hi = Ws[tx * (D + 1) + 2 * k2 + 1];
        float2 p = make_float2(lo, hi);
        w2[k2] = *reinterpret_cast<unsigned long long*>(&p);
    }
    __syncthreads();

    for (int rb = blockIdx.x * GEMM_ROWS; rb < N; rb += gridDim.x * GEMM_ROWS) {
        // load 32 rows x 64 floats = 2048 floats, float4-coalesced
        {
            const float4* src = reinterpret_cast<const float4*>(x + (size_t)rb * D);
            float4* dst = reinterpret_cast<float4*>(&xs[0][0]);
            int nvec = GEMM_ROWS * D / 4;                  // 512
            int limit = (N - rb) * (D / 4);                // guard tail
            for (int v = tid; v < nvec; v += 256) {
                if (v < limit) dst[v] = src[v];
            }
        }
        __syncthreads();

        int r0 = ty * RPT;                   // local row base for this thread
        unsigned long long acc[RPT];
#pragma unroll
        for (int i = 0; i < RPT; i++) acc[i] = 0ULL;

#pragma unroll
        for (int k2 = 0; k2 < D / 2; k2++) {
            unsigned long long wreg = w2[k2];
#pragma unroll
            for (int i = 0; i < RPT; i++) {
                float2 xv = xs[r0 + i][k2];  // warp-broadcast (all lanes same addr)
                unsigned long long xp = *reinterpret_cast<unsigned long long*>(&xv);
                fma_f32x2(acc[i], xp, wreg, acc[i]);
            }
        }

#pragma unroll
        for (int i = 0; i < RPT; i++) {
            int r = rb + r0 + i;
            if (r < N) {
                float2 p = *reinterpret_cast<float2*>(&acc[i]);
                g_xh[(size_t)r * D + tx] = p.x + p.y;
            }
        }
        __syncthreads();
    }
}

// ---------------------------------------------------------------------------
// k4: edge scatter — one warp per edge, 64 RED.F32 per edge
// ---------------------------------------------------------------------------
__global__ void k_scatter(const int* __restrict__ ei, float* __restrict__ out, int E) {
    int gtid = blockIdx.x * blockDim.x + threadIdx.x;
    int warp = gtid >> 5;
    int lane = threadIdx.x & 31;
    int nwarps = (gridDim.x * blockDim.x) >> 5;

    const int* rowp = ei;
    const int* colp = ei + E;

    for (int e = warp; e < E; e += nwarps) {
        int r = rowp[e];
        int c = colp[e];
        float w = g_dinv[r] * g_dinv[c];
        const float* src = &g_xh[(size_t)c * D];
        float* dst = &out[(size_t)r * D];
        float v0 = w * src[lane];
        float v1 = w * src[lane + 32];
        atomicAdd(&dst[lane], v0);
        atomicAdd(&dst[lane + 32], v1);
    }
}

// ---------------------------------------------------------------------------
// launch
// ---------------------------------------------------------------------------
extern "C" void kernel_launch(void* const* d_in, const int* in_sizes, int n_in,
                              void* d_out, int out_size) {
    const int*   edge_index = (const int*)d_in[0];
    const float* x          = (const float*)d_in[1];
    const float* W          = (const float*)d_in[2];
    float*       out        = (float*)d_out;

    int E = in_sizes[0] / 2;
    int N = in_sizes[1] / D;

    k_zero<<<2048, 256>>>(out, out_size, N);
    k_degree<<<2048, 256>>>(edge_index, E);
    k_dinv<<<(N + 255) / 256, 256>>>(N);

    int gemm_blocks = (N + GEMM_ROWS - 1) / GEMM_ROWS;   // 3125
    k_gemm<<<gemm_blocks, 256>>>(x, W, N);

    k_scatter<<<4096, 256>>>(edge_index, out, E);
}

// round 5
// speedup vs baseline: 1.7755x; 1.2586x over previous
#include <cuda_runtime.h>
#include <cuda_bf16.h>

#define NMAX 100000
#define EMAX 1600000
#define D 64
#define SCAN_B 1024

// __device__ scratch (no allocations allowed)
__device__ int   g_deg[NMAX];       // int degree
__device__ int   g_rowstart[NMAX];  // exclusive prefix of degree
__device__ int   g_cursor[NMAX];    // fill cursors (copy of rowstart)
__device__ int   g_bsum[128];       // block sums for scan
__device__ float g_dinv[NMAX];
__device__ float g_xh[(size_t)NMAX * D];
__device__ int   g_ecol[EMAX];      // CSR column indices

// packed fp32x2 FMA (Blackwell)
__device__ __forceinline__ void fma_f32x2(unsigned long long& d,
                                          unsigned long long a,
                                          unsigned long long b,
                                          unsigned long long c) {
    asm("fma.rn.f32x2 %0, %1, %2, %3;" : "=l"(d) : "l"(a), "l"(b), "l"(c));
}

__device__ __forceinline__ unsigned smem_u32(const void* p) {
    return (unsigned)__cvta_generic_to_shared(p);
}
__device__ __forceinline__ void cp_async16(unsigned s, const void* g) {
    asm volatile("cp.async.cg.shared.global [%0], [%1], 16;" :: "r"(s), "l"(g));
}
__device__ __forceinline__ void cp_commit() { asm volatile("cp.async.commit_group;"); }
template <int N> __device__ __forceinline__ void cp_wait() {
    asm volatile("cp.async.wait_group %0;" :: "n"(N));
}

// ---------------------------------------------------------------------------
// zero degree
// ---------------------------------------------------------------------------
__global__ void k_zero(int N) {
    int i = blockIdx.x * blockDim.x + threadIdx.x;
    if (i < N) g_deg[i] = 0;
}

// ---------------------------------------------------------------------------
// degree histogram (int atomics)
// ---------------------------------------------------------------------------
__global__ void k_degree(const int* __restrict__ rowp, int E) {
    int i = blockIdx.x * blockDim.x + threadIdx.x;
    int stride = gridDim.x * blockDim.x;
    for (int e = i; e < E; e += stride) atomicAdd(&g_deg[rowp[e]], 1);
}

// ---------------------------------------------------------------------------
// dinv_sqrt
// ---------------------------------------------------------------------------
__global__ void k_dinv(int N) {
    int i = blockIdx.x * blockDim.x + threadIdx.x;
    if (i < N) {
        int d = g_deg[i];
        g_dinv[i] = (d > 0) ? rsqrtf((float)d) : 0.0f;
    }
}

// ---------------------------------------------------------------------------
// scan 1: per-block (1024) exclusive scan of g_deg -> g_rowstart, block sums
// ---------------------------------------------------------------------------
__global__ void k_scan1(int N) {
    __shared__ int sh[SCAN_B];
    int i = blockIdx.x * SCAN_B + threadIdx.x;
    int v = (i < N) ? g_deg[i] : 0;
    sh[threadIdx.x] = v;
    __syncthreads();
#pragma unroll
    for (int off = 1; off < SCAN_B; off <<= 1) {
        int t = (threadIdx.x >= off) ? sh[threadIdx.x - off] : 0;
        __syncthreads();
        if (threadIdx.x >= off) sh[threadIdx.x] += t;
        __syncthreads();
    }
    if (i < N) g_rowstart[i] = sh[threadIdx.x] - v;  // exclusive within block
    if (threadIdx.x == SCAN_B - 1) g_bsum[blockIdx.x] = sh[SCAN_B - 1];
}

// ---------------------------------------------------------------------------
// scan 2: single block, exclusive scan of block sums (nb <= 128)
// ---------------------------------------------------------------------------
__global__ void k_scan2(int nb) {
    __shared__ int sh[128];
    int v = (threadIdx.x < nb) ? g_bsum[threadIdx.x] : 0;
    sh[threadIdx.x] = v;
    __syncthreads();
#pragma unroll
    for (int off = 1; off < 128; off <<= 1) {
        int t = (threadIdx.x >= off) ? sh[threadIdx.x - off] : 0;
        __syncthreads();
        if (threadIdx.x >= off) sh[threadIdx.x] += t;
        __syncthreads();
    }
    if (threadIdx.x < nb) g_bsum[threadIdx.x] = sh[threadIdx.x] - v;  // exclusive
}

// ---------------------------------------------------------------------------
// scan 3: add block offsets; init cursors
// ---------------------------------------------------------------------------
__global__ void k_scan3(int N) {
    int i = blockIdx.x * blockDim.x + threadIdx.x;
    if (i < N) {
        int s = g_rowstart[i] + g_bsum[i / SCAN_B];
        g_rowstart[i] = s;
        g_cursor[i] = s;
    }
}

// ---------------------------------------------------------------------------
// CSR fill: atomic ticket per row, store column index
// ---------------------------------------------------------------------------
__global__ void k_fill(const int* __restrict__ ei, int E) {
    int i = blockIdx.x * blockDim.x + threadIdx.x;
    int stride = gridDim.x * blockDim.x;
    const int* rowp = ei;
    const int* colp = ei + E;
    for (int e = i; e < E; e += stride) {
        int r = rowp[e];
        int p = atomicAdd(&g_cursor[r], 1);
        g_ecol[p] = colp[e];
    }
}

// ---------------------------------------------------------------------------
// GEMM: xh = x @ W^T. Persistent blocks, W register-stationary (f32x2),
// cp.async double-buffered x tiles, 32 rows / tile, 8 rows / thread.
// ---------------------------------------------------------------------------
#define GEMM_ROWS 32
#define RPT 8
#define GEMM_GRID 296   // 148 SMs x 2 CTAs

__global__ void __launch_bounds__(256) k_gemm(const float* __restrict__ x,
                                              const float* __restrict__ W, int N) {
    __shared__ float  Ws[D * (D + 1)];
    __shared__ float2 xs[2][GEMM_ROWS][D / 2];   // ping-pong, 8KB each

    int tid = threadIdx.x;
    int tx = tid & 63;   // output feature
    int ty = tid >> 6;   // 0..3

    for (int i = tid; i < D * D; i += 256)
        Ws[(i >> 6) * (D + 1) + (i & 63)] = W[i];
    __syncthreads();

    unsigned long long w2[D / 2];
#pragma unroll
    for (int k2 = 0; k2 < D / 2; k2++) {
        float2 p = make_float2(Ws[tx * (D + 1) + 2 * k2], Ws[tx * (D + 1) + 2 * k2 + 1]);
        w2[k2] = *reinterpret_cast<unsigned long long*>(&p);
    }
    __syncthreads();

    int ntiles = (N + GEMM_ROWS - 1) / GEMM_ROWS;

    // issue loads for a tile into buffer buf (2 x 16B per thread)
    auto issue = [&](int t, int buf) {
        const float4* src = reinterpret_cast<const float4*>(x + (size_t)t * GEMM_ROWS * D);
        int limit = (N - t * GEMM_ROWS) * (D / 4);        // float4 count valid
        unsigned sbase = smem_u32(&xs[buf][0][0]);
#pragma unroll
        for (int rnd = 0; rnd < 2; rnd++) {
            int v = tid + rnd * 256;
            if (v < 512 && v < limit) cp_async16(sbase + v * 16, src + v);
        }
        cp_commit();
    };

    int t = blockIdx.x;
    if (t < ntiles) issue(t, 0);
    int buf = 0;

    for (; t < ntiles; t += GEMM_GRID) {
        int tn = t + GEMM_GRID;
        bool have_next = (tn < ntiles);
        if (have_next) issue(tn, buf ^ 1);

        if (have_next) cp_wait<1>(); else cp_wait<0>();
        __syncthreads();

        int r0 = ty * RPT;
        unsigned long long acc[RPT];
#pragma unroll
        for (int i = 0; i < RPT; i++) acc[i] = 0ULL;

#pragma unroll
        for (int k2 = 0; k2 < D / 2; k2++) {
            unsigned long long wreg = w2[k2];
#pragma unroll
            for (int i = 0; i < RPT; i++) {
                float2 xv = xs[buf][r0 + i][k2];   // warp broadcast
                unsigned long long xp = *reinterpret_cast<unsigned long long*>(&xv);
                fma_f32x2(acc[i], xp, wreg, acc[i]);
            }
        }

        int rb = t * GEMM_ROWS;
#pragma unroll
        for (int i = 0; i < RPT; i++) {
            int r = rb + r0 + i;
            if (r < N) {
                float2 p = *reinterpret_cast<float2*>(&acc[i]);
                g_xh[(size_t)r * D + tx] = p.x + p.y;
            }
        }
        __syncthreads();   // before this buffer is overwritten
        buf ^= 1;
    }
}

// ---------------------------------------------------------------------------
// Gather: warp per row, register accumulation, zero atomics.
// out[r] = dinv[r] * sum_j dinv[c_j] * xh[c_j]
// ---------------------------------------------------------------------------
__global__ void k_gather(float* __restrict__ out, int N) {
    int gtid = blockIdx.x * blockDim.x + threadIdx.x;
    int warp = gtid >> 5;
    int lane = threadIdx.x & 31;
    int nwarps = (gridDim.x * blockDim.x) >> 5;

    for (int r = warp; r < N; r += nwarps) {
        int s = g_rowstart[r];
        int e = s + g_deg[r];
        float a0 = 0.f, a1 = 0.f, b0 = 0.f, b1 = 0.f;
        int j = s;
        for (; j + 1 < e; j += 2) {
            int c0 = g_ecol[j];
            int c1 = g_ecol[j + 1];
            float d0 = g_dinv[c0];
            float d1 = g_dinv[c1];
            const float* p0 = g_xh + (size_t)c0 * D;
            const float* p1 = g_xh + (size_t)c1 * D;
            a0 = fmaf(d0, p0[lane], a0);
            a1 = fmaf(d0, p0[lane + 32], a1);
            b0 = fmaf(d1, p1[lane], b0);
            b1 = fmaf(d1, p1[lane + 32], b1);
        }
        if (j < e) {
            int c = g_ecol[j];
            float dd = g_dinv[c];
            const float* p = g_xh + (size_t)c * D;
            a0 = fmaf(dd, p[lane], a0);
            a1 = fmaf(dd, p[lane + 32], a1);
        }
        float dr = g_dinv[r];
        out[(size_t)r * D + lane]      = dr * (a0 + b0);
        out[(size_t)r * D + lane + 32] = dr * (a1 + b1);
    }
}

// ---------------------------------------------------------------------------
// launch
// ---------------------------------------------------------------------------
extern "C" void kernel_launch(void* const* d_in, const int* in_sizes, int n_in,
                              void* d_out, int out_size) {
    const int*   edge_index = (const int*)d_in[0];
    const float* x          = (const float*)d_in[1];
    const float* W          = (const float*)d_in[2];
    float*       out        = (float*)d_out;

    int E = in_sizes[0] / 2;
    int N = in_sizes[1] / D;
    int nb = (N + SCAN_B - 1) / SCAN_B;   // <= 128 for N <= 100000

    k_zero<<<(N + 255) / 256, 256>>>(N);
    k_degree<<<2048, 256>>>(edge_index, E);
    k_dinv<<<(N + 255) / 256, 256>>>(N);

    k_scan1<<<nb, SCAN_B>>>(N);
    k_scan2<<<1, 128>>>(nb);
    k_scan3<<<(N + 255) / 256, 256>>>(N);
    k_fill<<<2048, 256>>>(edge_index, E);

    k_gemm<<<GEMM_GRID, 256>>>(x, W, N);

    k_gather<<<2048, 256>>>(out, N);
}

// round 6
// speedup vs baseline: 2.0153x; 1.1350x over previous
#include <cuda_runtime.h>
#include <cuda_fp16.h>
#include <cuda_bf16.h>

#define NMAX 100000
#define EMAX 1600000
#define D 64
#define SCAN_B 1024

// __device__ scratch (no allocations allowed)
__device__ int    g_deg[NMAX];
__device__ int    g_rowstart[NMAX];
__device__ int    g_cursor[NMAX];
__device__ int    g_bsum[128];
__device__ float  g_dinv[NMAX];
__device__ __half g_xh[(size_t)NMAX * D];   // fp16, pre-scaled by dinv[node]
__device__ int    g_ecol[EMAX];

// packed fp32x2 FMA (Blackwell)
__device__ __forceinline__ void fma_f32x2(unsigned long long& d,
                                          unsigned long long a,
                                          unsigned long long b,
                                          unsigned long long c) {
    asm("fma.rn.f32x2 %0, %1, %2, %3;" : "=l"(d) : "l"(a), "l"(b), "l"(c));
}
__device__ __forceinline__ unsigned smem_u32(const void* p) {
    return (unsigned)__cvta_generic_to_shared(p);
}
__device__ __forceinline__ void cp_async16(unsigned s, const void* g) {
    asm volatile("cp.async.cg.shared.global [%0], [%1], 16;" :: "r"(s), "l"(g));
}
__device__ __forceinline__ void cp_commit() { asm volatile("cp.async.commit_group;"); }
template <int N> __device__ __forceinline__ void cp_wait() {
    asm volatile("cp.async.wait_group %0;" :: "n"(N));
}

// ---------------------------------------------------------------------------
__global__ void k_zero(int N) {
    int i = blockIdx.x * blockDim.x + threadIdx.x;
    if (i < N) g_deg[i] = 0;
}

__global__ void k_degree(const int* __restrict__ rowp, int E) {
    int i = blockIdx.x * blockDim.x + threadIdx.x;
    int stride = gridDim.x * blockDim.x;
    for (int e = i; e < E; e += stride) atomicAdd(&g_deg[rowp[e]], 1);
}

// ---------------------------------------------------------------------------
// scan 1: shuffle-based per-block (1024) scan of g_deg -> exclusive g_rowstart
// ---------------------------------------------------------------------------
__global__ void k_scan1(int N) {
    __shared__ int wsum[32];
    int i = blockIdx.x * SCAN_B + threadIdx.x;
    int lane = threadIdx.x & 31;
    int wid = threadIdx.x >> 5;

    int v = (i < N) ? g_deg[i] : 0;
    int s = v;
#pragma unroll
    for (int off = 1; off < 32; off <<= 1) {
        int t = __shfl_up_sync(0xffffffffu, s, off);
        if (lane >= off) s += t;
    }
    if (lane == 31) wsum[wid] = s;
    __syncthreads();
    if (wid == 0) {
        int ws = wsum[lane];
#pragma unroll
        for (int off = 1; off < 32; off <<= 1) {
            int t = __shfl_up_sync(0xffffffffu, ws, off);
            if (lane >= off) ws += t;
        }
        wsum[lane] = ws;   // inclusive warp sums
    }
    __syncthreads();
    int base = (wid > 0) ? wsum[wid - 1] : 0;
    int incl = s + base;
    if (i < N) g_rowstart[i] = incl - v;
    if (threadIdx.x == SCAN_B - 1) g_bsum[blockIdx.x] = incl;
}

// ---------------------------------------------------------------------------
// scan 2: single block, exclusive scan of block sums (nb <= 128)
// ---------------------------------------------------------------------------
__global__ void k_scan2(int nb) {
    __shared__ int sh[128];
    int v = (threadIdx.x < nb) ? g_bsum[threadIdx.x] : 0;
    sh[threadIdx.x] = v;
    __syncthreads();
#pragma unroll
    for (int off = 1; off < 128; off <<= 1) {
        int t = (threadIdx.x >= off) ? sh[threadIdx.x - off] : 0;
        __syncthreads();
        if (threadIdx.x >= off) sh[threadIdx.x] += t;
        __syncthreads();
    }
    if (threadIdx.x < nb) g_bsum[threadIdx.x] = sh[threadIdx.x] - v;
}

// ---------------------------------------------------------------------------
// scan 3: add block offsets; init cursors; compute dinv (fused)
// ---------------------------------------------------------------------------
__global__ void k_scan3(int N) {
    int i = blockIdx.x * blockDim.x + threadIdx.x;
    if (i < N) {
        int s = g_rowstart[i] + g_bsum[i / SCAN_B];
        g_rowstart[i] = s;
        g_cursor[i] = s;
        int d = g_deg[i];
        g_dinv[i] = (d > 0) ? rsqrtf((float)d) : 0.0f;
    }
}

// ---------------------------------------------------------------------------
// CSR fill: atomic ticket per row, store column index
// ---------------------------------------------------------------------------
__global__ void k_fill(const int* __restrict__ ei, int E) {
    int i = blockIdx.x * blockDim.x + threadIdx.x;
    int stride = gridDim.x * blockDim.x;
    const int* rowp = ei;
    const int* colp = ei + E;
    for (int e = i; e < E; e += stride) {
        int r = rowp[e];
        int p = atomicAdd(&g_cursor[r], 1);
        g_ecol[p] = colp[e];
    }
}

// ---------------------------------------------------------------------------
// GEMM: xh_h[r] = fp16( dinv[r] * (x[r] @ W^T) ).  Persistent, W-stationary
// (f32x2), cp.async double-buffered tiles, 32 rows/tile, 8 rows/thread.
// ---------------------------------------------------------------------------
#define GEMM_ROWS 32
#define RPT 8
#define GEMM_GRID 296

__global__ void __launch_bounds__(256) k_gemm(const float* __restrict__ x,
                                              const float* __restrict__ W, int N) {
    __shared__ float  Ws[D * (D + 1)];
    __shared__ float2 xs[2][GEMM_ROWS][D / 2];

    int tid = threadIdx.x;
    int tx = tid & 63;
    int ty = tid >> 6;

    for (int i = tid; i < D * D; i += 256)
        Ws[(i >> 6) * (D + 1) + (i & 63)] = W[i];
    __syncthreads();

    unsigned long long w2[D / 2];
#pragma unroll
    for (int k2 = 0; k2 < D / 2; k2++) {
        float2 p = make_float2(Ws[tx * (D + 1) + 2 * k2], Ws[tx * (D + 1) + 2 * k2 + 1]);
        w2[k2] = *reinterpret_cast<unsigned long long*>(&p);
    }
    __syncthreads();

    int ntiles = (N + GEMM_ROWS - 1) / GEMM_ROWS;

    auto issue = [&](int t, int buf) {
        const float4* src = reinterpret_cast<const float4*>(x + (size_t)t * GEMM_ROWS * D);
        int limit = (N - t * GEMM_ROWS) * (D / 4);
        unsigned sbase = smem_u32(&xs[buf][0][0]);
#pragma unroll
        for (int rnd = 0; rnd < 2; rnd++) {
            int v = tid + rnd * 256;
            if (v < 512 && v < limit) cp_async16(sbase + v * 16, src + v);
        }
        cp_commit();
    };

    int t = blockIdx.x;
    if (t < ntiles) issue(t, 0);
    int buf = 0;

    for (; t < ntiles; t += GEMM_GRID) {
        int tn = t + GEMM_GRID;
        bool have_next = (tn < ntiles);
        if (have_next) issue(tn, buf ^ 1);

        if (have_next) cp_wait<1>(); else cp_wait<0>();
        __syncthreads();

        int r0 = ty * RPT;
        unsigned long long acc[RPT];
#pragma unroll
        for (int i = 0; i < RPT; i++) acc[i] = 0ULL;

#pragma unroll
        for (int k2 = 0; k2 < D / 2; k2++) {
            unsigned long long wreg = w2[k2];
#pragma unroll
            for (int i = 0; i < RPT; i++) {
                float2 xv = xs[buf][r0 + i][k2];
                unsigned long long xp = *reinterpret_cast<unsigned long long*>(&xv);
                fma_f32x2(acc[i], xp, wreg, acc[i]);
            }
        }

        int rb = t * GEMM_ROWS;
#pragma unroll
        for (int i = 0; i < RPT; i++) {
            int r = rb + r0 + i;
            if (r < N) {
                float2 p = *reinterpret_cast<float2*>(&acc[i]);
                float dr = g_dinv[r];            // pre-scale by this node's dinv
                g_xh[(size_t)r * D + tx] = __float2half_rn(dr * (p.x + p.y));
            }
        }
        __syncthreads();
        buf ^= 1;
    }
}

// ---------------------------------------------------------------------------
// Gather: warp per row. xh rows are fp16 + pre-scaled, so inner loop is a
// pure half2 -> float2 accumulate. One half2 (4B) per lane per edge.
// out[r] = dinv[r] * sum_j xh_h[c_j]
// ---------------------------------------------------------------------------
__global__ void k_gather(float* __restrict__ out, int N) {
    int gtid = blockIdx.x * blockDim.x + threadIdx.x;
    int warp = gtid >> 5;
    int lane = threadIdx.x & 31;
    int nwarps = (gridDim.x * blockDim.x) >> 5;

    const __half2* xh2 = reinterpret_cast<const __half2*>(g_xh);

    for (int r = warp; r < N; r += nwarps) {
        int s = g_rowstart[r];
        int e = s + g_deg[r];

        float ax = 0.f, ay = 0.f, bx = 0.f, by = 0.f;
        float cx = 0.f, cy = 0.f, dx = 0.f, dy = 0.f;

        int j = s;
        for (; j + 3 < e; j += 4) {
            int c0 = g_ecol[j];
            int c1 = g_ecol[j + 1];
            int c2 = g_ecol[j + 2];
            int c3 = g_ecol[j + 3];
            float2 f0 = __half22float2(xh2[(size_t)c0 * 32 + lane]);
            float2 f1 = __half22float2(xh2[(size_t)c1 * 32 + lane]);
            float2 f2 = __half22float2(xh2[(size_t)c2 * 32 + lane]);
            float2 f3 = __half22float2(xh2[(size_t)c3 * 32 + lane]);
            ax += f0.x; ay += f0.y;
            bx += f1.x; by += f1.y;
            cx += f2.x; cy += f2.y;
            dx += f3.x; dy += f3.y;
        }
        for (; j < e; j++) {
            int c = g_ecol[j];
            float2 f = __half22float2(xh2[(size_t)c * 32 + lane]);
            ax += f.x; ay += f.y;
        }

        float dr = g_dinv[r];
        float2 res = make_float2(dr * (ax + bx + cx + dx),
                                 dr * (ay + by + cy + dy));
        reinterpret_cast<float2*>(out)[(size_t)r * 32 + lane] = res;
    }
}

// ---------------------------------------------------------------------------
// launch
// ---------------------------------------------------------------------------
extern "C" void kernel_launch(void* const* d_in, const int* in_sizes, int n_in,
                              void* d_out, int out_size) {
    const int*   edge_index = (const int*)d_in[0];
    const float* x          = (const float*)d_in[1];
    const float* W          = (const float*)d_in[2];
    float*       out        = (float*)d_out;

    int E = in_sizes[0] / 2;
    int N = in_sizes[1] / D;
    int nb = (N + SCAN_B - 1) / SCAN_B;

    k_zero<<<(N + 255) / 256, 256>>>(N);
    k_degree<<<2048, 256>>>(edge_index, E);
    k_scan1<<<nb, SCAN_B>>>(N);
    k_scan2<<<1, 128>>>(nb);
    k_scan3<<<(N + 255) / 256, 256>>>(N);
    k_fill<<<2048, 256>>>(edge_index, E);
    k_gemm<<<GEMM_GRID, 256>>>(x, W, N);
    k_gather<<<2048, 256>>>(out, N);
}